// round 1
// baseline (speedup 1.0000x reference)
#include <cuda_runtime.h>
#include <math.h>

// Problem constants
#define BB   8
#define NL   64
#define NT   512
#define KDIM 256          // 2*C input features
#define NH   256          // concatenated hidden (128 A + 128 B)
#define TM   64           // rows per CTA
#define NBLK ((BB*NL*NT)/TM)   // 4096

// Per-block partial sums [block][4] : vdw, hbond_raw, metal_raw, hphob_raw
__device__ float g_partial[NBLK][4];

__global__ __launch_bounds__(256, 2)
void energy_fused_kernel(
    const float* __restrict__ lig_pos,   // [B,NL,3]
    const float* __restrict__ tgt_pos,   // [B,NT,3]
    const float* __restrict__ lig_r,     // [B,NL]
    const float* __restrict__ tgt_r,     // [B,NT]
    const float* __restrict__ lig_nm,    // [B,NL]
    const float* __restrict__ tgt_nm,    // [B,NT]
    const float* __restrict__ inter,     // [B,3,NL,NT]
    const float* __restrict__ h_cat,     // [B*NL*NT, 256]
    const float* __restrict__ WA1,       // [256,128]
    const float* __restrict__ bA1,       // [128]
    const float* __restrict__ WA2,       // [128]
    const float* __restrict__ bA2,       // [1]
    const float* __restrict__ WB1,       // [256,128]
    const float* __restrict__ bB1,       // [128]
    const float* __restrict__ WB2,       // [128]
    const float* __restrict__ bB2)       // [1]
{
    __shared__ float Xs[16][TM];       // [k][row]
    __shared__ float Ws[16][NH];       // [k][j]
    __shared__ float red[TM][33];      // row partial dots (padded)
    __shared__ float blockred[2][4];

    const int tid = threadIdx.x;
    const int ty  = tid >> 5;          // 0..7  (row group)
    const int tx  = tid & 31;          // 0..31 (col group)
    const int j0  = tx * 8;
    const long row0 = (long)blockIdx.x * TM;

    // accumulators, init with layer-1 bias
    float acc[8][8];
    #pragma unroll
    for (int jj = 0; jj < 8; jj++) {
        int j = j0 + jj;
        float bias = (j < 128) ? bA1[j] : bB1[j - 128];
        #pragma unroll
        for (int i = 0; i < 8; i++) acc[i][jj] = bias;
    }

    // ---- main GEMM loop over K in chunks of 16 ----
    for (int k0 = 0; k0 < KDIM; k0 += 16) {
        // load X tile (64 rows x 16 k), transposed into Xs[k][row]
        {
            int r  = tid >> 2;             // 0..63
            int kc = (tid & 3) * 4;        // 0,4,8,12
            float4 v = *(const float4*)(h_cat + (row0 + r) * (long)KDIM + k0 + kc);
            Xs[kc + 0][r] = v.x;
            Xs[kc + 1][r] = v.y;
            Xs[kc + 2][r] = v.z;
            Xs[kc + 3][r] = v.w;
        }
        // load W tile (16 k x 256 j) from WA1 | WB1
        #pragma unroll
        for (int it = 0; it < 4; it++) {
            int idx = tid + it * 256;      // 0..1023
            int c   = idx >> 6;            // 0..15
            int jj  = idx & 63;            // float4 column index
            float4 v;
            if (jj < 32) v = *(const float4*)(WA1 + (long)(k0 + c) * 128 + jj * 4);
            else         v = *(const float4*)(WB1 + (long)(k0 + c) * 128 + (jj - 32) * 4);
            *(float4*)(&Ws[c][jj * 4]) = v;
        }
        __syncthreads();

        #pragma unroll
        for (int k = 0; k < 16; k++) {
            float xr[8], wr[8];
            *(float4*)(xr)     = *(const float4*)(&Xs[k][ty * 8]);
            *(float4*)(xr + 4) = *(const float4*)(&Xs[k][ty * 8 + 4]);
            *(float4*)(wr)     = *(const float4*)(&Ws[k][j0]);
            *(float4*)(wr + 4) = *(const float4*)(&Ws[k][j0 + 4]);
            #pragma unroll
            for (int i = 0; i < 8; i++)
                #pragma unroll
                for (int jj = 0; jj < 8; jj++)
                    acc[i][jj] = fmaf(xr[i], wr[jj], acc[i][jj]);
        }
        __syncthreads();
    }

    // ---- layer 2: relu + dot with W2, partials per row ----
    {
        float p[8];
        #pragma unroll
        for (int i = 0; i < 8; i++) p[i] = 0.0f;
        #pragma unroll
        for (int jj = 0; jj < 8; jj++) {
            int j = j0 + jj;
            float w2 = (j < 128) ? WA2[j] : WB2[j - 128];
            #pragma unroll
            for (int i = 0; i < 8; i++)
                p[i] = fmaf(fmaxf(acc[i][jj], 0.0f), w2, p[i]);
        }
        #pragma unroll
        for (int i = 0; i < 8; i++)
            red[ty * 8 + i][tx] = p[i];
    }
    __syncthreads();

    // ---- per-pair physics epilogue (threads 0..63, one per row) ----
    float v_vdw = 0.f, v_hb = 0.f, v_mt = 0.f, v_hp = 0.f;
    if (tid < TM) {
        int r = tid;
        float sA = 0.f, sB = 0.f;
        #pragma unroll
        for (int x = 0; x < 16; x++) { sA += red[r][x]; sB += red[r][x + 16]; }
        float mlpA = sA + bA2[0];
        float mlpB = sB + bB2[0];

        long grow = row0 + r;
        int b   = (int)(grow >> 15);       // / (NL*NT)
        int rem = (int)(grow & 32767);
        int l   = rem >> 9;                // / NT
        int t   = rem & 511;

        const float* lp = lig_pos + ((long)b * NL + l) * 3;
        const float* tp = tgt_pos + ((long)b * NT + t) * 3;
        float dx = lp[0] - tp[0];
        float dy = lp[1] - tp[1];
        float dz = lp[2] - tp[2];
        float dm = sqrtf(dx*dx + dy*dy + dz*dz + 1e-10f);
        if (dm < 0.5f) dm = 1e10f;

        float Bp  = tanhf(mlpB) * 0.2f;
        float dm0 = lig_r[b * NL + l] + tgt_r[b * NT + t] + Bp;
        float dm0c = (dm0 < 1e-4f) ? 1.0f : dm0;
        float ratio = dm0c / dm;
        float r2 = ratio * ratio;
        float r6 = r2 * r2 * r2;
        float vdwe = fminf(fmaf(r6, r6, -2.0f * r6), 100.0f);
        vdwe *= lig_nm[b * NL + l] * tgt_nm[b * NT + t];

        float Av   = 1.0f / (1.0f + expf(-mlpA));
        float Avdw = Av * (0.0356f - 0.0178f) + 0.0178f;
        v_vdw = Avdw * vdwe;

        float d = dm - dm0;
        const float* ib = inter + (long)b * 3 * NL * NT + (long)l * NT + t;
        float I0 = ib[0];
        float I1 = ib[NL * NT];
        float I2 = ib[2 * NL * NT];
        v_hb = fminf(fmaxf(d * I0 * (-1.0f / 0.7f), 0.0f), 1.0f);
        v_mt = fminf(fmaxf(d * I1 * (-1.0f / 0.7f), 0.0f), 1.0f);
        v_hp = fminf(fmaxf((1.5f - d) * I2, 0.0f), 1.0f);

        // warp-level reduction (warps 0 and 1 fully active here)
        #pragma unroll
        for (int off = 16; off > 0; off >>= 1) {
            v_vdw += __shfl_down_sync(0xffffffffu, v_vdw, off);
            v_hb  += __shfl_down_sync(0xffffffffu, v_hb,  off);
            v_mt  += __shfl_down_sync(0xffffffffu, v_mt,  off);
            v_hp  += __shfl_down_sync(0xffffffffu, v_hp,  off);
        }
        if ((tid & 31) == 0) {
            int w = tid >> 5;
            blockred[w][0] = v_vdw;
            blockred[w][1] = v_hb;
            blockred[w][2] = v_mt;
            blockred[w][3] = v_hp;
        }
    }
    __syncthreads();
    if (tid < 4)
        g_partial[blockIdx.x][tid] = blockred[0][tid] + blockred[1][tid];
}

__global__ void energy_reduce_kernel(
    const float* __restrict__ rotor,     // [B]
    const float* __restrict__ hb_c,      // [1]
    const float* __restrict__ hp_c,      // [1]
    const float* __restrict__ rot_c,     // [1]
    float* __restrict__ out)             // [B,4]
{
    // 256 threads: b = tid/32, k = (tid/8)%4, s = tid%8
    int tid = threadIdx.x;
    int b = tid >> 5;
    int k = (tid >> 3) & 3;
    int s = tid & 7;
    const int BLK_PER_B = NBLK / BB;     // 512
    float sum = 0.f;
    for (int i = s; i < BLK_PER_B; i += 8)
        sum += g_partial[b * BLK_PER_B + i][k];
    sum += __shfl_down_sync(0xffffffffu, sum, 4);
    sum += __shfl_down_sync(0xffffffffu, sum, 2);
    sum += __shfl_down_sync(0xffffffffu, sum, 1);
    if (s == 0) {
        float v = sum;
        float hb2 = hb_c[0] * hb_c[0];
        float hp2 = hp_c[0] * hp_c[0];
        if (k == 1 || k == 2) v *= -hb2;
        if (k == 3)           v *= -hp2;
        v /= (1.0f + rot_c[0] * rot_c[0] * rotor[b]);
        out[b * 4 + k] = v;
    }
}

extern "C" void kernel_launch(void* const* d_in, const int* in_sizes, int n_in,
                              void* d_out, int out_size)
{
    const float* lig_pos = (const float*)d_in[0];
    const float* tgt_pos = (const float*)d_in[1];
    const float* lig_r   = (const float*)d_in[2];
    const float* tgt_r   = (const float*)d_in[3];
    const float* lig_nm  = (const float*)d_in[4];
    const float* tgt_nm  = (const float*)d_in[5];
    const float* inter   = (const float*)d_in[6];
    const float* rotor   = (const float*)d_in[7];
    const float* h_cat   = (const float*)d_in[8];
    const float* WA1     = (const float*)d_in[9];
    const float* bA1     = (const float*)d_in[10];
    const float* WA2     = (const float*)d_in[11];
    const float* bA2     = (const float*)d_in[12];
    const float* WB1     = (const float*)d_in[13];
    const float* bB1     = (const float*)d_in[14];
    const float* WB2     = (const float*)d_in[15];
    const float* bB2     = (const float*)d_in[16];
    const float* hb_c    = (const float*)d_in[17];
    const float* hp_c    = (const float*)d_in[18];
    const float* rot_c   = (const float*)d_in[19];
    float* out = (float*)d_out;

    energy_fused_kernel<<<NBLK, 256>>>(
        lig_pos, tgt_pos, lig_r, tgt_r, lig_nm, tgt_nm, inter, h_cat,
        WA1, bA1, WA2, bA2, WB1, bB1, WB2, bB2);
    energy_reduce_kernel<<<1, 256>>>(rotor, hb_c, hp_c, rot_c, out);
}